// round 5
// baseline (speedup 1.0000x reference)
#include <cuda_runtime.h>
#include <cuda_bf16.h>
#include <cstdint>
#include <cstddef>

// Problem constants
#define T_STEPS 64
#define NROWS   8192
#define RTILE   64
#define NCTA    (NROWS / RTILE)   // 128
#define NTHR    512

// ---- SMEM layout (bytes) ----
// A_hi : [64 rows][520 bf16]  (512 data + 8 pad)  = 66560 B   @ 0
// A_lo : same                                      = 66560 B   @ 66560
// W_s  : 3 bufs x 32 KB fragment-linear            = 98304 B   @ 133120
#define A_ROW_B   1040         // 520 bf16
#define ALO_OFF   66560
#define W_OFF     133120
#define SMEM_BYTES 231424

// W fragments: [chunk16][split2][kt2][ntg32][lane32][word2] uint32 (hi split=0, lo split=1)
__device__ uint32_t g_Wfrag[16 * 2 * 2 * 32 * 32 * 2];   // 131072 words = 512 KB
__device__ float    g_bias[256];

__global__ void prep_kernel(const float* __restrict__ W_ih,
                            const float* __restrict__ W_hh,
                            const float* __restrict__ b_ih,
                            const float* __restrict__ b_hh) {
    int idx = blockIdx.x * blockDim.x + threadIdx.x;
    if (idx < 65536) {
        int w     = idx & 1;
        int lane  = (idx >> 1) & 31;
        int ntg   = (idx >> 6) & 31;
        int kt2   = (idx >> 11) & 1;
        int chunk = idx >> 12;                       // 0..15
        int k = chunk * 32 + kt2 * 16 + (lane & 3) * 2 + w * 8;
        int n = ntg * 8 + (lane >> 2);
        float v0, v1;
        if (k < 256) { v0 = W_ih[n * 256 + k];       v1 = W_ih[n * 256 + k + 1]; }
        else         { v0 = W_hh[n * 256 + k - 256]; v1 = W_hh[n * 256 + k - 255]; }
        __nv_bfloat16 h0 = __float2bfloat16_rn(v0);
        __nv_bfloat16 h1 = __float2bfloat16_rn(v1);
        float r0 = v0 - __bfloat162float(h0);
        float r1 = v1 - __bfloat162float(h1);
        __nv_bfloat162 hiw; hiw.x = h0; hiw.y = h1;
        __nv_bfloat162 low = __floats2bfloat162_rn(r0, r1);
        int base = chunk * 8192 + kt2 * 2048 + ntg * 64 + lane * 2 + w;
        g_Wfrag[base]        = *reinterpret_cast<uint32_t*>(&hiw);   // hi split
        g_Wfrag[base + 4096] = *reinterpret_cast<uint32_t*>(&low);   // lo split
    }
    if (idx < 256) g_bias[idx] = b_ih[idx] + b_hh[idx];
}

// ---- helpers ----
__device__ __forceinline__ uint32_t bf2_hi(float a, float b) {
    __nv_bfloat162 t = __floats2bfloat162_rn(a, b);
    return *reinterpret_cast<uint32_t*>(&t);
}
__device__ __forceinline__ uint32_t bf2_lo(float a, float b) {
    float ra = a - __bfloat162float(__float2bfloat16_rn(a));
    float rb = b - __bfloat162float(__float2bfloat16_rn(b));
    __nv_bfloat162 t = __floats2bfloat162_rn(ra, rb);
    return *reinterpret_cast<uint32_t*>(&t);
}
__device__ __forceinline__ float2 unp_add(uint32_t uh, uint32_t ul) {
    __nv_bfloat162 h = *reinterpret_cast<__nv_bfloat162*>(&uh);
    __nv_bfloat162 l = *reinterpret_cast<__nv_bfloat162*>(&ul);
    float2 r;
    r.x = __bfloat162float(h.x) + __bfloat162float(l.x);
    r.y = __bfloat162float(h.y) + __bfloat162float(l.y);
    return r;
}

#define CP_COMMIT() asm volatile("cp.async.commit_group;\n" ::: "memory")
#define CP_WAIT1()  asm volatile("cp.async.wait_group 1;\n" ::: "memory")
#define CP_WAIT0()  asm volatile("cp.async.wait_group 0;\n" ::: "memory")

__device__ __forceinline__ void cp16(void* dst_s, const void* src_g) {
    unsigned a = (unsigned)__cvta_generic_to_shared(dst_s);
    asm volatile("cp.async.ca.shared.global [%0], [%1], 16;\n" :: "r"(a), "l"(src_g));
}

#define LDSM4(r, addr)                                                          \
    asm volatile("ldmatrix.sync.aligned.m8n8.x4.shared.b16 {%0,%1,%2,%3}, [%4];" \
                 : "=r"((r)[0]), "=r"((r)[1]), "=r"((r)[2]), "=r"((r)[3])        \
                 : "r"(addr))

#define MMA16816(c, a, b0, b1)                                                   \
    asm volatile("mma.sync.aligned.m16n8k16.row.col.f32.bf16.bf16.f32 "          \
                 "{%0,%1,%2,%3}, {%4,%5,%6,%7}, {%8,%9}, {%0,%1,%2,%3};"         \
                 : "+f"((c)[0]), "+f"((c)[1]), "+f"((c)[2]), "+f"((c)[3])        \
                 : "r"((a)[0]), "r"((a)[1]), "r"((a)[2]), "r"((a)[3]),           \
                   "r"(b0), "r"(b1))

// Epilogue: h = (relu?)(C + bias), split to bf16 hi/lo, store into A cols 256..511.
// Warp tile 16x64: rows wm*16 + (lane>>2) and +8; cols wn*64 + nt*8 + (lane&3)*2.
__device__ __forceinline__ void epi_store(float (&c)[8][4], const float* bias_r,
                                          char* smem, int wm, int wn, int lane,
                                          bool relu) {
    int r = wm * 16 + (lane >> 2);
    #pragma unroll
    for (int nt = 0; nt < 8; ++nt) {
        int j = wn * 64 + nt * 8 + (lane & 3) * 2;
        float b0 = bias_r[nt * 2], b1 = bias_r[nt * 2 + 1];
        float h00 = c[nt][0] + b0, h01 = c[nt][1] + b1;
        float h10 = c[nt][2] + b0, h11 = c[nt][3] + b1;
        if (relu) {
            h00 = fmaxf(h00, 0.0f); h01 = fmaxf(h01, 0.0f);
            h10 = fmaxf(h10, 0.0f); h11 = fmaxf(h11, 0.0f);
        }
        char* p0 = smem + r * A_ROW_B + 512 + j * 2;
        char* p1 = p0 + 8 * A_ROW_B;
        *reinterpret_cast<uint32_t*>(p0)           = bf2_hi(h00, h01);
        *reinterpret_cast<uint32_t*>(p0 + ALO_OFF) = bf2_lo(h00, h01);
        *reinterpret_cast<uint32_t*>(p1)           = bf2_hi(h10, h11);
        *reinterpret_cast<uint32_t*>(p1 + ALO_OFF) = bf2_lo(h10, h11);
    }
}

__global__ void __launch_bounds__(NTHR, 1)
rnn_fused_kernel(const float* __restrict__ X,
                 const float* __restrict__ lnw,
                 const float* __restrict__ lnb,
                 float* __restrict__ out) {
    extern __shared__ char smem[];
    uint32_t a_hi_u = (uint32_t)__cvta_generic_to_shared(smem);
    uint32_t* W_u32 = reinterpret_cast<uint32_t*>(smem + W_OFF);

    const int tid  = threadIdx.x;
    const int lane = tid & 31;
    const int warp = tid >> 5;      // 0..15
    const int wm   = warp >> 2;     // 0..3  (16-row block)
    const int wn   = warp & 3;      // 0..3  (64-col block)
    const int row0 = blockIdx.x * RTILE;

    // Per-thread constants from global (indices thread-fixed; no smem needed)
    float bias_r[16];
    #pragma unroll
    for (int nt = 0; nt < 8; ++nt) {
        int j = wn * 64 + nt * 8 + (lane & 3) * 2;
        bias_r[nt * 2]     = g_bias[j];
        bias_r[nt * 2 + 1] = g_bias[j + 1];
    }
    float lnw_r[8], lnb_r[8];
    #pragma unroll
    for (int jj = 0; jj < 8; ++jj) {
        lnw_r[jj] = __ldg(lnw + lane * 8 + jj);
        lnb_r[jj] = __ldg(lnb + lane * 8 + jj);
    }

    const int f4 = tid & 63;   // float4 column index (0..63)
    const int rb = tid >> 6;   // base row (0..7)

    float c[8][4];

    for (int t = 0; t < T_STEPS; ++t) {
        // ---- stage X_t -> A_hi/A_lo cols 0..255 (disjoint from LN reads) ----
        const float* Xt = X + ((size_t)t * NROWS + row0) * 256;
        #pragma unroll
        for (int i = 0; i < 8; ++i) {
            int r = rb + i * 8;
            float4 v = *reinterpret_cast<const float4*>(Xt + r * 256 + f4 * 4);
            uint2 hw, lw;
            hw.x = bf2_hi(v.x, v.y); hw.y = bf2_hi(v.z, v.w);
            lw.x = bf2_lo(v.x, v.y); lw.y = bf2_lo(v.z, v.w);
            char* p = smem + r * A_ROW_B + f4 * 8;
            *reinterpret_cast<uint2*>(p)           = hw;
            *reinterpret_cast<uint2*>(p + ALO_OFF) = lw;
        }

        #pragma unroll
        for (int nt = 0; nt < 8; ++nt)
            #pragma unroll
            for (int q = 0; q < 4; ++q) c[nt][q] = 0.0f;

        // ---- W ring prologue: chunks 0,1 -> bufs 0,1 ----
        #pragma unroll
        for (int ch = 0; ch < 2; ++ch) {
            const char* src = reinterpret_cast<const char*>(g_Wfrag) + ch * 32768;
            char* dst = smem + W_OFF + ch * 32768;
            #pragma unroll
            for (int q = 0; q < 4; ++q) {
                int i4 = tid + (q << 9);
                cp16(dst + i4 * 16, src + i4 * 16);
            }
            CP_COMMIT();
        }

        #pragma unroll 1
        for (int chunk = 0; chunk < 16; ++chunk) {
            if (chunk < 15) CP_WAIT1(); else CP_WAIT0();
            __syncthreads();
            // Barrier proved compute(chunk-1) done -> buf (chunk+2)%3 is free.
            if (chunk + 2 < 16) {
                int ch = chunk + 2;
                const char* src = reinterpret_cast<const char*>(g_Wfrag) + ch * 32768;
                char* dst = smem + W_OFF + (ch % 3) * 32768;
                #pragma unroll
                for (int q = 0; q < 4; ++q) {
                    int i4 = tid + (q << 9);
                    cp16(dst + i4 * 16, src + i4 * 16);
                }
                CP_COMMIT();
            }

            // ---- compute this k32 chunk ----
            {
                const uint32_t* Wb = W_u32 + (chunk % 3) * 8192;
                const int kbyte = chunk << 6;   // 32 bf16 cols * 2B
                #pragma unroll
                for (int kt = 0; kt < 2; ++kt) {
                    uint32_t ah[4], al[4];
                    int row = wm * 16 + (lane & 15);
                    uint32_t ad = a_hi_u + row * A_ROW_B + kbyte + kt * 32
                                + ((lane >> 4) << 4);
                    LDSM4(ah, ad);
                    LDSM4(al, ad + ALO_OFF);
                    const uint32_t* pb = Wb + (kt << 11) + (wn << 3) * 64 + (lane << 1);
                    #pragma unroll
                    for (int nt = 0; nt < 8; ++nt) {
                        uint32_t bh0 = pb[0],    bh1 = pb[1];
                        uint32_t bl0 = pb[4096], bl1 = pb[4097];
                        MMA16816(c[nt], ah, bh0, bh1);
                        MMA16816(c[nt], ah, bl0, bl1);
                        MMA16816(c[nt], al, bh0, bh1);
                        pb += 64;
                    }
                }
            }

            // t==0: after the X half, seed h0 = Xw0 + b_ih + b_hh (no relu).
            // Own-tile write; published to other warps by iter-8's barrier.
            if (t == 0 && chunk == 7)
                epi_store(c, bias_r, smem, wm, wn, lane, false);
        }

        __syncthreads();   // all chunk-15 computes done before h overwrite
        // ---- h_new = relu(C + bias) -> A cols 256..511 ----
        epi_store(c, bias_r, smem, wm, wn, lane, true);
        __syncthreads();   // publish h for LN (cross-warp rows)

        // ---- LayerNorm + coalesced output: warp handles rows warp*4..warp*4+3 ----
        float* outT = out + ((size_t)t * NROWS + row0) * 256;
        #pragma unroll 1
        for (int i = 0; i < 4; ++i) {
            int r = warp * 4 + i;
            const char* ph = smem + r * A_ROW_B + 512 + lane * 16;
            uint4 hw = *reinterpret_cast<const uint4*>(ph);
            uint4 lw = *reinterpret_cast<const uint4*>(ph + ALO_OFF);
            float v[8];
            { float2 u = unp_add(hw.x, lw.x); v[0] = u.x; v[1] = u.y; }
            { float2 u = unp_add(hw.y, lw.y); v[2] = u.x; v[3] = u.y; }
            { float2 u = unp_add(hw.z, lw.z); v[4] = u.x; v[5] = u.y; }
            { float2 u = unp_add(hw.w, lw.w); v[6] = u.x; v[7] = u.y; }
            float s = 0.0f, s2 = 0.0f;
            #pragma unroll
            for (int jj = 0; jj < 8; ++jj) { s += v[jj]; s2 += v[jj] * v[jj]; }
            #pragma unroll
            for (int o = 16; o > 0; o >>= 1) {
                s  += __shfl_xor_sync(0xffffffffu, s,  o);
                s2 += __shfl_xor_sync(0xffffffffu, s2, o);
            }
            float mean = s  * (1.0f / 256.0f);
            float var  = s2 * (1.0f / 256.0f) - mean * mean;
            float rstd = rsqrtf(var + 1e-5f);
            float o8[8];
            #pragma unroll
            for (int jj = 0; jj < 8; ++jj)
                o8[jj] = (v[jj] - mean) * rstd * lnw_r[jj] + lnb_r[jj];
            float4 w0 = make_float4(o8[0], o8[1], o8[2], o8[3]);
            float4 w1 = make_float4(o8[4], o8[5], o8[6], o8[7]);
            *reinterpret_cast<float4*>(outT + r * 256 + lane * 8)     = w0;
            *reinterpret_cast<float4*>(outT + r * 256 + lane * 8 + 4) = w1;
        }
        // Next step: X staging touches A cols 0..255 (disjoint from LN's 256..511);
        // W prologue bufs 0,1 were last read at chunks 15/13, fenced by the
        // pre-epi barrier. Chunk-0 compute is fenced by iter-0's barrier.
    }
}

extern "C" void kernel_launch(void* const* d_in, const int* in_sizes, int n_in,
                              void* d_out, int out_size) {
    const float* X    = (const float*)d_in[0];
    const float* W_ih = (const float*)d_in[1];
    const float* W_hh = (const float*)d_in[2];
    const float* b_ih = (const float*)d_in[3];
    const float* b_hh = (const float*)d_in[4];
    const float* lnw  = (const float*)d_in[5];
    const float* lnb  = (const float*)d_in[6];
    float* out = (float*)d_out;

    (void)in_sizes; (void)n_in; (void)out_size;

    prep_kernel<<<256, 256>>>(W_ih, W_hh, b_ih, b_hh);

    cudaFuncSetAttribute(rnn_fused_kernel,
                         cudaFuncAttributeMaxDynamicSharedMemorySize, SMEM_BYTES);
    rnn_fused_kernel<<<NCTA, NTHR, SMEM_BYTES>>>(X, lnw, lnb, out);
}

// round 7
// speedup vs baseline: 1.3781x; 1.3781x over previous
#include <cuda_runtime.h>
#include <cuda_bf16.h>
#include <cstdint>
#include <cstddef>

// Problem constants
#define T_STEPS 64
#define NROWS   8192
#define RTILE   64
#define NCTA    (NROWS / RTILE)   // 128
#define NTHR    512

// ---- SMEM layout (bytes) ----
// A_hi : [64 rows][520 bf16]  = 66560 B @ 0
// A_lo : same                 = 66560 B @ 66560
// W    : 4 groups x ring3 x 8192 B = 98304 B @ 133120
#define A_ROW_B   1040
#define ALO_OFF   66560
#define W_OFF     133120
#define SMEM_BYTES 231424

// W fragments, grouped by output-column group:
// idx bits: [group:2][chunk:4][split:1][kt:1][ntg:3][lane:5][w:1]  (131072 words)
// k = chunk*32 + kt*16 + (lane&3)*2 + w*8 ;  n = group*64 + ntg*8 + (lane>>2)
__device__ uint32_t g_Wfrag[131072];   // 512 KB
__device__ float    g_bias[256];

__global__ void prep_kernel(const float* __restrict__ W_ih,
                            const float* __restrict__ W_hh,
                            const float* __restrict__ b_ih,
                            const float* __restrict__ b_hh) {
    int idx = blockIdx.x * blockDim.x + threadIdx.x;
    if (idx < 131072) {
        int w     = idx & 1;
        int lane  = (idx >> 1) & 31;
        int ntg   = (idx >> 6) & 7;
        int kt    = (idx >> 9) & 1;
        int split = (idx >> 10) & 1;
        int chunk = (idx >> 11) & 15;
        int group = idx >> 15;
        int k = chunk * 32 + kt * 16 + (lane & 3) * 2 + w * 8;
        int n = group * 64 + ntg * 8 + (lane >> 2);
        float v0, v1;
        if (k < 256) { v0 = W_ih[n * 256 + k];       v1 = W_ih[n * 256 + k + 1]; }
        else         { v0 = W_hh[n * 256 + k - 256]; v1 = W_hh[n * 256 + k - 255]; }
        __nv_bfloat16 h0 = __float2bfloat16_rn(v0);
        __nv_bfloat16 h1 = __float2bfloat16_rn(v1);
        uint32_t val;
        if (split == 0) {
            __nv_bfloat162 hp; hp.x = h0; hp.y = h1;
            val = *reinterpret_cast<uint32_t*>(&hp);
        } else {
            __nv_bfloat162 lp = __floats2bfloat162_rn(v0 - __bfloat162float(h0),
                                                      v1 - __bfloat162float(h1));
            val = *reinterpret_cast<uint32_t*>(&lp);
        }
        g_Wfrag[idx] = val;
    }
    if (idx < 256) g_bias[idx] = b_ih[idx] + b_hh[idx];
}

// ---- helpers ----
__device__ __forceinline__ uint32_t bf2_hi(float a, float b) {
    __nv_bfloat162 t = __floats2bfloat162_rn(a, b);
    return *reinterpret_cast<uint32_t*>(&t);
}
__device__ __forceinline__ uint32_t bf2_lo(float a, float b) {
    float ra = a - __bfloat162float(__float2bfloat16_rn(a));
    float rb = b - __bfloat162float(__float2bfloat16_rn(b));
    __nv_bfloat162 t = __floats2bfloat162_rn(ra, rb);
    return *reinterpret_cast<uint32_t*>(&t);
}
__device__ __forceinline__ float2 unp_add(uint32_t uh, uint32_t ul) {
    __nv_bfloat162 h = *reinterpret_cast<__nv_bfloat162*>(&uh);
    __nv_bfloat162 l = *reinterpret_cast<__nv_bfloat162*>(&ul);
    float2 r;
    r.x = __bfloat162float(h.x) + __bfloat162float(l.x);
    r.y = __bfloat162float(h.y) + __bfloat162float(l.y);
    return r;
}

#define CP_COMMIT() asm volatile("cp.async.commit_group;\n" ::: "memory")
#define CP_WAIT1()  asm volatile("cp.async.wait_group 1;\n" ::: "memory")
#define CP_WAIT0()  asm volatile("cp.async.wait_group 0;\n" ::: "memory")
__device__ __forceinline__ void cp16(void* dst_s, const void* src_g) {
    unsigned a = (unsigned)__cvta_generic_to_shared(dst_s);
    asm volatile("cp.async.cg.shared.global [%0], [%1], 16;\n" :: "r"(a), "l"(src_g));
}
#define BAR_G(id) asm volatile("bar.sync %0, %1;" :: "r"(id), "r"(128) : "memory")

#define LDSM4(r, addr)                                                          \
    asm volatile("ldmatrix.sync.aligned.m8n8.x4.shared.b16 {%0,%1,%2,%3}, [%4];" \
                 : "=r"((r)[0]), "=r"((r)[1]), "=r"((r)[2]), "=r"((r)[3])        \
                 : "r"(addr))

#define MMA16816(c, a, b0, b1)                                                   \
    asm volatile("mma.sync.aligned.m16n8k16.row.col.f32.bf16.bf16.f32 "          \
                 "{%0,%1,%2,%3}, {%4,%5,%6,%7}, {%8,%9}, {%0,%1,%2,%3};"         \
                 : "+f"((c)[0]), "+f"((c)[1]), "+f"((c)[2]), "+f"((c)[3])        \
                 : "r"((a)[0]), "r"((a)[1]), "r"((a)[2]), "r"((a)[3]),           \
                   "r"(b0), "r"(b1))

// Epilogue: h = (relu?)(C + bias), split bf16 hi/lo -> A cols 256..511.
// Warp tile 16x64: rows wm*16 + (lane>>2), +8; cols wn*64 + nt*8 + (lane&3)*2.
__device__ __forceinline__ void epi_store(float (&c)[8][4], const float* bias_r,
                                          char* smem, int wm, int wn, int lane,
                                          bool relu) {
    int r = wm * 16 + (lane >> 2);
    #pragma unroll
    for (int nt = 0; nt < 8; ++nt) {
        int j = wn * 64 + nt * 8 + (lane & 3) * 2;
        float b0 = bias_r[nt * 2], b1 = bias_r[nt * 2 + 1];
        float h00 = c[nt][0] + b0, h01 = c[nt][1] + b1;
        float h10 = c[nt][2] + b0, h11 = c[nt][3] + b1;
        if (relu) {
            h00 = fmaxf(h00, 0.0f); h01 = fmaxf(h01, 0.0f);
            h10 = fmaxf(h10, 0.0f); h11 = fmaxf(h11, 0.0f);
        }
        char* p0 = smem + r * A_ROW_B + 512 + j * 2;
        char* p1 = p0 + 8 * A_ROW_B;
        *reinterpret_cast<uint32_t*>(p0)           = bf2_hi(h00, h01);
        *reinterpret_cast<uint32_t*>(p0 + ALO_OFF) = bf2_lo(h00, h01);
        *reinterpret_cast<uint32_t*>(p1)           = bf2_hi(h10, h11);
        *reinterpret_cast<uint32_t*>(p1 + ALO_OFF) = bf2_lo(h10, h11);
    }
}

__global__ void __launch_bounds__(NTHR, 1)
rnn_fused_kernel(const float* __restrict__ X,
                 const float* __restrict__ lnw,
                 const float* __restrict__ lnb,
                 float* __restrict__ out) {
    extern __shared__ char smem[];
    uint32_t a_hi_u = (uint32_t)__cvta_generic_to_shared(smem);

    const int tid  = threadIdx.x;
    const int lane = tid & 31;
    const int warp = tid >> 5;      // 0..15
    const int wm   = warp & 3;      // 16-row block; also SMSP index
    const int g    = warp >> 2;     // output-column group (= wn)
    const int bid  = g + 1;         // named barrier id
    const int row0 = blockIdx.x * RTILE;

    // Per-thread constants (indices thread-fixed)
    float bias_r[16];
    #pragma unroll
    for (int nt = 0; nt < 8; ++nt) {
        int j = g * 64 + nt * 8 + (lane & 3) * 2;
        bias_r[nt * 2]     = g_bias[j];
        bias_r[nt * 2 + 1] = g_bias[j + 1];
    }
    float lnw_r[8], lnb_r[8];
    #pragma unroll
    for (int jj = 0; jj < 8; ++jj) {
        lnw_r[jj] = __ldg(lnw + lane * 8 + jj);
        lnb_r[jj] = __ldg(lnb + lane * 8 + jj);
    }

    const int f4 = tid & 63;   // float4 column index (0..63)
    const int rb = tid >> 6;   // base row (0..7)

    // group-private W ring addresses
    const char* wsrc_base = reinterpret_cast<const char*>(g_Wfrag) + g * 131072;
    char* wring = smem + W_OFF + g * 24576;
    const uint32_t* wring_u32 = reinterpret_cast<const uint32_t*>(wring);

    float c[8][4];

    for (int t = 0; t < T_STEPS; ++t) {
        // ---- W ring prologue (group-private): chunks 0,1 -> bufs 0,1 ----
        #pragma unroll
        for (int ch = 0; ch < 2; ++ch) {
            const char* src = wsrc_base + ch * 8192;
            char* dst = wring + ch * 8192;
            #pragma unroll
            for (int q = 0; q < 4; ++q) {
                int i4 = wm * 128 + q * 32 + lane;
                cp16(dst + i4 * 16, src + i4 * 16);
            }
            CP_COMMIT();
        }

        // ---- stage X_t -> A_hi/A_lo cols 0..255 (CTA-wide) ----
        const float* Xt = X + ((size_t)t * NROWS + row0) * 256;
        #pragma unroll
        for (int i = 0; i < 8; ++i) {
            int r = rb + i * 8;
            float4 v = *reinterpret_cast<const float4*>(Xt + r * 256 + f4 * 4);
            uint2 hw, lw;
            hw.x = bf2_hi(v.x, v.y); hw.y = bf2_hi(v.z, v.w);
            lw.x = bf2_lo(v.x, v.y); lw.y = bf2_lo(v.z, v.w);
            char* p = smem + r * A_ROW_B + f4 * 8;
            *reinterpret_cast<uint2*>(p)           = hw;
            *reinterpret_cast<uint2*>(p + ALO_OFF) = lw;
        }

        #pragma unroll
        for (int nt = 0; nt < 8; ++nt)
            #pragma unroll
            for (int q = 0; q < 4; ++q) c[nt][q] = 0.0f;

        __syncthreads();   // X published for all groups

        // ---- chunk loop: per-group pipeline, named barriers only ----
        #pragma unroll 1
        for (int chunk = 0; chunk < 16; ++chunk) {
            if (chunk < 15) CP_WAIT1(); else CP_WAIT0();
            BAR_G(bid);   // group's 4 warps: chunk resident, buf (chunk+2)%3 free

            if (chunk + 2 < 16) {
                int ch = chunk + 2;
                const char* src = wsrc_base + ch * 8192;
                char* dst = wring + (ch % 3) * 8192;
                #pragma unroll
                for (int q = 0; q < 4; ++q) {
                    int i4 = wm * 128 + q * 32 + lane;
                    cp16(dst + i4 * 16, src + i4 * 16);
                }
                CP_COMMIT();
            }

            // ---- compute this k32 chunk ----
            {
                const uint32_t* Wb = wring_u32 + (chunk % 3) * 2048;
                const int kbyte = chunk << 6;
                #pragma unroll
                for (int kt = 0; kt < 2; ++kt) {
                    uint32_t ah[4], al[4];
                    int row = wm * 16 + (lane & 15);
                    uint32_t ad = a_hi_u + row * A_ROW_B + kbyte + kt * 32
                                + ((lane >> 4) << 4);
                    LDSM4(ah, ad);
                    LDSM4(al, ad + ALO_OFF);
                    const uint32_t* pb = Wb + (kt << 9) + (lane << 1);
                    #pragma unroll
                    for (int nt = 0; nt < 8; ++nt) {
                        uint32_t bh0 = pb[0],    bh1 = pb[1];
                        uint32_t bl0 = pb[1024], bl1 = pb[1025];
                        MMA16816(c[nt], ah, bh0, bh1);
                        MMA16816(c[nt], ah, bl0, bl1);
                        MMA16816(c[nt], al, bh0, bh1);
                        pb += 64;
                    }
                }
            }

            // t==0: seed h0 = Xw0 + bias (no relu) after the X half.
            // CTA-wide: all groups must finish chunk 7 before h is written,
            // and h must be published before chunk 8 reads it.
            if (t == 0 && chunk == 7) {
                __syncthreads();
                epi_store(c, bias_r, smem, wm, g, lane, false);
                __syncthreads();
            }
        }

        __syncthreads();   // all groups done reading h before overwrite
        epi_store(c, bias_r, smem, wm, g, lane, true);
        __syncthreads();   // h published (next step + LN)

        // ---- LayerNorm + coalesced output: warp handles rows warp*4..+3 ----
        float* outT = out + ((size_t)t * NROWS + row0) * 256;
        #pragma unroll 1
        for (int i = 0; i < 4; ++i) {
            int r = warp * 4 + i;
            const char* ph = smem + r * A_ROW_B + 512 + lane * 16;
            uint4 hw = *reinterpret_cast<const uint4*>(ph);
            uint4 lw = *reinterpret_cast<const uint4*>(ph + ALO_OFF);
            float v[8];
            { float2 u = unp_add(hw.x, lw.x); v[0] = u.x; v[1] = u.y; }
            { float2 u = unp_add(hw.y, lw.y); v[2] = u.x; v[3] = u.y; }
            { float2 u = unp_add(hw.z, lw.z); v[4] = u.x; v[5] = u.y; }
            { float2 u = unp_add(hw.w, lw.w); v[6] = u.x; v[7] = u.y; }
            float s = 0.0f, s2 = 0.0f;
            #pragma unroll
            for (int jj = 0; jj < 8; ++jj) { s += v[jj]; s2 += v[jj] * v[jj]; }
            #pragma unroll
            for (int o = 16; o > 0; o >>= 1) {
                s  += __shfl_xor_sync(0xffffffffu, s,  o);
                s2 += __shfl_xor_sync(0xffffffffu, s2, o);
            }
            float mean = s  * (1.0f / 256.0f);
            float var  = s2 * (1.0f / 256.0f) - mean * mean;
            float rstd = rsqrtf(var + 1e-5f);
            float o8[8];
            #pragma unroll
            for (int jj = 0; jj < 8; ++jj)
                o8[jj] = (v[jj] - mean) * rstd * lnw_r[jj] + lnb_r[jj];
            float4 w0 = make_float4(o8[0], o8[1], o8[2], o8[3]);
            float4 w1 = make_float4(o8[4], o8[5], o8[6], o8[7]);
            *reinterpret_cast<float4*>(outT + r * 256 + lane * 8)     = w0;
            *reinterpret_cast<float4*>(outT + r * 256 + lane * 8 + 4) = w1;
        }
        // Next step: X staging (cols 0..255) is disjoint from LN reads (256..511);
        // W bufs 0,1 were last read at chunks 15/13 (before pre-epi barrier).
    }
}

extern "C" void kernel_launch(void* const* d_in, const int* in_sizes, int n_in,
                              void* d_out, int out_size) {
    const float* X    = (const float*)d_in[0];
    const float* W_ih = (const float*)d_in[1];
    const float* W_hh = (const float*)d_in[2];
    const float* b_ih = (const float*)d_in[3];
    const float* b_hh = (const float*)d_in[4];
    const float* lnw  = (const float*)d_in[5];
    const float* lnb  = (const float*)d_in[6];
    float* out = (float*)d_out;

    (void)in_sizes; (void)n_in; (void)out_size;

    prep_kernel<<<512, 256>>>(W_ih, W_hh, b_ih, b_hh);

    cudaFuncSetAttribute(rnn_fused_kernel,
                         cudaFuncAttributeMaxDynamicSharedMemorySize, SMEM_BYTES);
    rnn_fused_kernel<<<NCTA, NTHR, SMEM_BYTES>>>(X, lnw, lnb, out);
}